// round 3
// baseline (speedup 1.0000x reference)
#include <cuda_runtime.h>

#define T_STEPS 1024
#define BATCH   2048
#define N1      30
#define N2      60

using ull = unsigned long long;

// packed fp32x2 FMA (Blackwell): d = a*b + c on two fp32 lanes of a 64-bit reg
__device__ __forceinline__ ull ffma2(ull a, ull b, ull c) {
    ull d;
    asm("fma.rn.f32x2 %0, %1, %2, %3;" : "=l"(d) : "l"(a), "l"(b), "l"(c));
    return d;
}
__device__ __forceinline__ ull pk2(float x, float y) {
    ull r;
    asm("mov.b64 %0, {%1, %2};" : "=l"(r) : "f"(x), "f"(y));
    return r;
}
__device__ __forceinline__ float hadd2(ull v) {
    float a, b;
    asm("mov.b64 {%0, %1}, %2;" : "=f"(a), "=f"(b) : "l"(v));
    return a + b;
}
// fast tanh, ~1e-6 rel err. Pre-activations here are bounded |x| < ~11, no clamp needed.
__device__ __forceinline__ float ftanh(float x) {
    float e = __expf(-2.f * x);
    return __fdividef(1.f - e, 1.f + e);
}

// Block = 64 threads (2 warps) = one "group" owning batch pair (b0, b0+1).
// Lane gid<60 owns r2 row gid (W22 row + masked W21 row in regs).
// Lane gid<30 (warp 0) additionally owns r1 row gid (W11 row in regs).
__global__ void __launch_bounds__(64, 6) hier_rnn_kernel(
    const float* __restrict__ inp,    // (T, B, 1)
    const float* __restrict__ noise1, // (T, B, N1)
    const float* __restrict__ noise2, // (T, B, N2)
    const float* __restrict__ W11,    // (N1, N1)
    const float* __restrict__ W22,    // (N2, N2)
    const float* __restrict__ W21,    // (N2, N1)
    const float* __restrict__ M21,    // (N2, N1)
    const float* __restrict__ Win,    // (N1,)
    const float* __restrict__ Wout,   // (N2,)
    float* __restrict__ out)          // (T, B, 1)
{
    __shared__ __align__(16) float s1[2][32];   // r1 state, per batch elem
    __shared__ __align__(16) float s2[2][64];   // r2 state, per batch elem
    __shared__ float2 ypart[2];                 // per-warp y partials

    const int gid  = threadIdx.x;       // 0..63
    const int warp = gid >> 5;
    const int b0   = blockIdx.x * 2;

    const bool act2 = gid < N2;         // owns an r2 row
    const bool act1 = gid < N1;         // owns an r1 row (warp 0 only)
    const int  row2 = act2 ? gid : 0;
    const int  row1 = act1 ? gid : 0;

    // ---- weights in registers, j-packed as f32x2 pairs ----
    ull w22p[30], w21p[15], w11p[15];
    #pragma unroll
    for (int k = 0; k < 30; k++) {
        float2 w = act2 ? *(const float2*)(W22 + row2 * N2 + 2 * k) : make_float2(0.f, 0.f);
        w22p[k] = pk2(w.x, w.y);
    }
    #pragma unroll
    for (int k = 0; k < 15; k++) {
        float2 w = act2 ? *(const float2*)(W21 + row2 * N1 + 2 * k) : make_float2(0.f, 0.f);
        float2 m = act2 ? *(const float2*)(M21 + row2 * N1 + 2 * k) : make_float2(0.f, 0.f);
        w21p[k] = pk2(w.x * m.x, w.y * m.y);
    }
    #pragma unroll
    for (int k = 0; k < 15; k++) {
        float2 w = act1 ? *(const float2*)(W11 + row1 * N1 + 2 * k) : make_float2(0.f, 0.f);
        w11p[k] = pk2(w.x, w.y);
    }
    const float winl  = act1 ? Win[row1]  : 0.f;
    const float woutl = act2 ? Wout[row2] : 0.f;

    // ---- zero state ----
    if (gid < 32) { s1[0][gid] = 0.f; s1[1][gid] = 0.f; }
    s2[0][gid] = 0.f;
    s2[1][gid] = 0.f;

    // ---- streaming pointers (lane-specific row; batch pair via imm offsets) ----
    const float* pn1 = noise1 + (long long)b0 * N1 + row1;
    const float* pn2 = noise2 + (long long)b0 * N2 + row2;
    const float* px  = inp + b0;
    float*       py  = out + b0;

    float2 xv   = *(const float2*)px;           // b0 even -> 8B aligned, broadcast
    float  n1v0 = __ldg(pn1);
    float  n1v1 = __ldg(pn1 + N1);
    float  n2v0 = __ldg(pn2);
    float  n2v1 = __ldg(pn2 + N2);

    const ulonglong2* v2_0 = (const ulonglong2*)s2[0];
    const ulonglong2* v2_1 = (const ulonglong2*)s2[1];
    const ulonglong2* v1_0 = (const ulonglong2*)s1[0];
    const ulonglong2* v1_1 = (const ulonglong2*)s1[1];
    const ull* s1w_0 = (const ull*)s1[0];
    const ull* s1w_1 = (const ull*)s1[1];

    __syncthreads();

    for (int t = 0; t < T_STEPS; t++) {
        // ---- phase A: W22 . r2_old  (both warps, 2 independent chains) ----
        ull acc0 = 0, acc1 = 0;
        #pragma unroll
        for (int k = 0; k < 15; k++) {
            ulonglong2 u0 = v2_0[k];
            ulonglong2 u1 = v2_1[k];
            acc0 = ffma2(w22p[2 * k],     u0.x, acc0);
            acc0 = ffma2(w22p[2 * k + 1], u0.y, acc0);
            acc1 = ffma2(w22p[2 * k],     u1.x, acc1);
            acc1 = ffma2(w22p[2 * k + 1], u1.y, acc1);
        }

        // ---- phase B: r1 update (warp 0 only) ----
        if (warp == 0) {
            ull a10 = 0, a11 = 0;
            #pragma unroll
            for (int k = 0; k < 7; k++) {
                ulonglong2 u0 = v1_0[k];
                ulonglong2 u1 = v1_1[k];
                a10 = ffma2(w11p[2 * k],     u0.x, a10);
                a10 = ffma2(w11p[2 * k + 1], u0.y, a10);
                a11 = ffma2(w11p[2 * k],     u1.x, a11);
                a11 = ffma2(w11p[2 * k + 1], u1.y, a11);
            }
            a10 = ffma2(w11p[14], s1w_0[14], a10);
            a11 = ffma2(w11p[14], s1w_1[14], a11);
            float r1n0 = ftanh(fmaf(winl, xv.x, n1v0) + hadd2(a10));
            float r1n1 = ftanh(fmaf(winl, xv.y, n1v1) + hadd2(a11));
            __syncwarp();                 // old-r1 reads done before publish
            if (act1) { s1[0][gid] = r1n0; s1[1][gid] = r1n1; }
        }

        // reload r1-side inputs for NEXT step (now one full step ahead of use)
        if (t + 1 < T_STEPS) {
            px  += BATCH;
            pn1 += BATCH * N1;
            xv   = *(const float2*)px;
            n1v0 = __ldg(pn1);
            n1v1 = __ldg(pn1 + N1);
        }

        __syncthreads();                  // r1_new visible to both warps

        // ---- phase C: += W21m . r1_new ----
        #pragma unroll
        for (int k = 0; k < 7; k++) {
            ulonglong2 u0 = v1_0[k];
            ulonglong2 u1 = v1_1[k];
            acc0 = ffma2(w21p[2 * k],     u0.x, acc0);
            acc0 = ffma2(w21p[2 * k + 1], u0.y, acc0);
            acc1 = ffma2(w21p[2 * k],     u1.x, acc1);
            acc1 = ffma2(w21p[2 * k + 1], u1.y, acc1);
        }
        acc0 = ffma2(w21p[14], s1w_0[14], acc0);
        acc1 = ffma2(w21p[14], s1w_1[14], acc1);

        float r2n0 = ftanh(n2v0 + hadd2(acc0));
        float r2n1 = ftanh(n2v1 + hadd2(acc1));

        if (act2) { s2[0][gid] = r2n0; s2[1][gid] = r2n1; }

        // reload r2-side noise for NEXT step
        if (t + 1 < T_STEPS) {
            pn2 += BATCH * N2;
            n2v0 = __ldg(pn2);
            n2v1 = __ldg(pn2 + N2);
        }

        // ---- y partials: per-warp shuffle reduction ----
        float yp0 = woutl * r2n0;
        float yp1 = woutl * r2n1;
        #pragma unroll
        for (int o = 16; o > 0; o >>= 1) {
            yp0 += __shfl_xor_sync(0xffffffffu, yp0, o);
            yp1 += __shfl_xor_sync(0xffffffffu, yp1, o);
        }
        if ((gid & 31) == 0) ypart[warp] = make_float2(yp0, yp1);

        __syncthreads();                  // r2_new + ypart visible

        // y finalize on an idle lane, off the recurrence critical path
        if (gid == 63) {
            float2 pa = ypart[0], pb = ypart[1];
            *(float2*)py = make_float2(pa.x + pb.x, pa.y + pb.y);
        }
        py += BATCH;
    }
}

extern "C" void kernel_launch(void* const* d_in, const int* in_sizes, int n_in,
                              void* d_out, int out_size)
{
    const float *inp = nullptr, *n1 = nullptr, *n2 = nullptr;
    const float *W11 = nullptr, *W22 = nullptr, *W21 = nullptr, *M21 = nullptr;
    const float *Win = nullptr, *Wout = nullptr;

    for (int i = 0; i < n_in; i++) {
        const float* p = (const float*)d_in[i];
        switch (in_sizes[i]) {
            case T_STEPS * BATCH:          inp = p; break;        // 2,097,152
            case T_STEPS * BATCH * N1:     n1  = p; break;        // 62,914,560
            case T_STEPS * BATCH * N2:     n2  = p; break;        // 125,829,120
            case N1 * N1:                  W11 = p; break;        // 900
            case N2 * N2:                  W22 = p; break;        // 3600
            case N2 * N1:                                          // 1800 (x2)
                if (!W21) W21 = p; else M21 = p;                   // order-robust: product commutes
                break;
            case N1:                       Win = p; break;         // 30
            case N2:                       Wout = p; break;        // 60
        }
    }

    // 1024 blocks x 64 threads; each block owns batch pair (2b, 2b+1)
    hier_rnn_kernel<<<BATCH / 2, 64>>>(inp, n1, n2, W11, W22, W21, M21, Win, Wout,
                                       (float*)d_out);
}